// round 1
// baseline (speedup 1.0000x reference)
#include <cuda_runtime.h>
#include <cuda_bf16.h>

#define HID 20
#define NTHREADS 256

__device__ __forceinline__ float tanh_ap(float x) {
    float y;
    asm("tanh.approx.f32 %0, %1;" : "=f"(y) : "f"(x));
    return y;
}

// sigmoid(z) where zh = 0.5*z was computed directly (0.5 folded into weights)
__device__ __forceinline__ float sig_from_half(float zh) {
    return fmaf(0.5f, tanh_ap(zh), 0.5f);
}

__global__ void __launch_bounds__(NTHREADS)
lstm_opt_kernel(const float* __restrict__ params,
                const float* __restrict__ grads,
                const float* __restrict__ h0,
                const float* __restrict__ c0,
                const float* __restrict__ W_ih,   // [80,2] row-major
                const float* __restrict__ W_hh,   // [80,20] row-major
                const float* __restrict__ b_ih,   // [80]
                const float* __restrict__ b_hh,   // [80]
                const float* __restrict__ W_out,  // [20]
                const float* __restrict__ b_out,  // [1]
                float* __restrict__ out,
                int n)
{
    // Shared weights. Sigmoid gate rows (i:0-19, f:20-39, o:60-79) are pre-scaled
    // by 0.5 so sigmoid(z) = 0.5*tanh(z_half)+0.5 needs no extra multiply.
    __shared__ float sWih[160];    // [row*2 + col]
    __shared__ float sB[80];       // (b_ih+b_hh), scaled
    __shared__ float sWhh[1600];   // [row*20 + m], scaled
    __shared__ float sWo[HID];
    __shared__ float sbo;

    const int t = threadIdx.x;
    for (int idx = t; idx < 160; idx += NTHREADS) {
        int row = idx >> 1;
        float s = (row >= 40 && row < 60) ? 1.0f : 0.5f;
        sWih[idx] = W_ih[idx] * s;
    }
    for (int idx = t; idx < 80; idx += NTHREADS) {
        float s = (idx >= 40 && idx < 60) ? 1.0f : 0.5f;
        sB[idx] = (b_ih[idx] + b_hh[idx]) * s;
    }
    for (int idx = t; idx < 1600; idx += NTHREADS) {
        int row = idx / 20;
        float s = (row >= 40 && row < 60) ? 1.0f : 0.5f;
        sWhh[idx] = W_hh[idx] * s;
    }
    if (t < HID) sWo[t] = W_out[t];
    if (t == 0)  sbo = b_out[0];
    __syncthreads();

    const int i = blockIdx.x * NTHREADS + t;
    if (i >= n) return;

    const float g = grads[i];
    const float p = params[i];

    // h0/c0 rows: 20 floats = 80 bytes, 16B aligned -> 5x float4
    float hv[HID], cv[HID];
    {
        const float4* h4 = reinterpret_cast<const float4*>(h0 + (size_t)i * HID);
        const float4* c4 = reinterpret_cast<const float4*>(c0 + (size_t)i * HID);
        #pragma unroll
        for (int q = 0; q < 5; q++) {
            float4 hh = h4[q];
            hv[4*q+0] = hh.x; hv[4*q+1] = hh.y; hv[4*q+2] = hh.z; hv[4*q+3] = hh.w;
            float4 cc = c4[q];
            cv[4*q+0] = cc.x; cv[4*q+1] = cc.y; cv[4*q+2] = cc.z; cv[4*q+3] = cc.w;
        }
    }

    // h-row zero test (values, so +-0 both count as zero)
    float habs = 0.0f;
    #pragma unroll
    for (int k = 0; k < HID; k++) habs += fabsf(hv[k]);
    const bool hzero = (habs == 0.0f);

    float acc = sbo;

    if (__builtin_expect(hzero, 1)) {
        // ---- fast path: h0 row is exactly zero -> no W_hh matvec ----
        #pragma unroll
        for (int k = 0; k < HID; k++) {
            const int ri = k, rg = 40 + k, ro = 60 + k;
            float zi = fmaf(sWih[2*ri], g, fmaf(sWih[2*ri+1], p, sB[ri])); // halved
            float zg = fmaf(sWih[2*rg], g, fmaf(sWih[2*rg+1], p, sB[rg]));
            float zo = fmaf(sWih[2*ro], g, fmaf(sWih[2*ro+1], p, sB[ro])); // halved

            float ik = sig_from_half(zi);
            float gk = tanh_ap(zg);
            float ok = sig_from_half(zo);

            float c1 = ik * gk;
            float ck = cv[k];
            if (ck != 0.0f) {
                const int rf = 20 + k;
                float zf = fmaf(sWih[2*rf], g, fmaf(sWih[2*rf+1], p, sB[rf])); // halved
                c1 = fmaf(sig_from_half(zf), ck, c1);
            }
            acc = fmaf(ok * tanh_ap(c1), sWo[k], acc);
        }
    } else {
        // ---- general path: full W_hh matvec (rare; kept compact) ----
        #pragma unroll 1
        for (int k = 0; k < HID; k++) {
            const int ri = k, rf = 20 + k, rg = 40 + k, ro = 60 + k;
            float zi = fmaf(sWih[2*ri], g, fmaf(sWih[2*ri+1], p, sB[ri]));
            float zf = fmaf(sWih[2*rf], g, fmaf(sWih[2*rf+1], p, sB[rf]));
            float zg = fmaf(sWih[2*rg], g, fmaf(sWih[2*rg+1], p, sB[rg]));
            float zo = fmaf(sWih[2*ro], g, fmaf(sWih[2*ro+1], p, sB[ro]));
            #pragma unroll 1
            for (int m = 0; m < HID; m++) {
                float hm = hv[m];
                zi = fmaf(sWhh[ri*HID + m], hm, zi);
                zf = fmaf(sWhh[rf*HID + m], hm, zf);
                zg = fmaf(sWhh[rg*HID + m], hm, zg);
                zo = fmaf(sWhh[ro*HID + m], hm, zo);
            }
            float ik = sig_from_half(zi);
            float fk = sig_from_half(zf);
            float gk = tanh_ap(zg);
            float ok = sig_from_half(zo);
            float c1 = fmaf(fk, cv[k], ik * gk);
            acc = fmaf(ok * tanh_ap(c1), sWo[k], acc);
        }
    }

    out[i] = acc;
}

extern "C" void kernel_launch(void* const* d_in, const int* in_sizes, int n_in,
                              void* d_out, int out_size)
{
    const float* params = (const float*)d_in[0];
    const float* grads  = (const float*)d_in[1];
    const float* h0     = (const float*)d_in[2];
    const float* c0     = (const float*)d_in[3];
    const float* W_ih   = (const float*)d_in[4];
    const float* W_hh   = (const float*)d_in[5];
    const float* b_ih   = (const float*)d_in[6];
    const float* b_hh   = (const float*)d_in[7];
    const float* W_out  = (const float*)d_in[8];
    const float* b_out  = (const float*)d_in[9];
    float* out = (float*)d_out;

    int n = in_sizes[0];
    int blocks = (n + NTHREADS - 1) / NTHREADS;
    lstm_opt_kernel<<<blocks, NTHREADS>>>(params, grads, h0, c0,
                                          W_ih, W_hh, b_ih, b_hh,
                                          W_out, b_out, out, n);
}

// round 2
// speedup vs baseline: 1.0277x; 1.0277x over previous
#include <cuda_runtime.h>
#include <cuda_bf16.h>

#define HID 20
#define NT 256

__device__ __forceinline__ float tanh_ap(float x) {
    float y;
    asm("tanh.approx.f32 %0, %1;" : "=f"(y) : "f"(x));
    return y;
}

// sigmoid(z) where zh = 0.5*z was computed directly (0.5 folded into weights)
__device__ __forceinline__ float sig_from_half(float zh) {
    return fmaf(0.5f, tanh_ap(zh), 0.5f);
}

__global__ void __launch_bounds__(NT, 4)
lstm_opt_kernel(const float* __restrict__ params,
                const float* __restrict__ grads,
                const float* __restrict__ h0,
                const float* __restrict__ c0,
                const float* __restrict__ W_ih,   // [80,2]
                const float* __restrict__ W_hh,   // [80,20]
                const float* __restrict__ b_ih,   // [80]
                const float* __restrict__ b_hh,   // [80]
                const float* __restrict__ W_out,  // [20]
                const float* __restrict__ b_out,  // [1]
                float* __restrict__ out,
                int n)
{
    // h/c staging: 256 rows x 20 floats, accessed as float4 (stride-5 granules,
    // conflict-free for both the coalesced fill and the per-row v4 reads).
    __shared__ float4 sH4[NT * 5];
    __shared__ float4 sC4[NT * 5];
    // Per-k packed weights: 16 floats per k -> 4x LDS.128 broadcast per k.
    // layout: [0]=wi_g [1]=wi_p [2]=bi (halved) | [3]=wg_g [4]=wg_p [5]=bg |
    //         [6]=wo_g [7]=wo_p [8]=bo (halved) | [9]=wf_g [10]=wf_p [11]=bf (halved) |
    //         [12]=W_out[k] [13..15]=pad
    __shared__ float sPack[HID][16];
    __shared__ float sWhh[1600];   // scaled; for rare general path
    __shared__ float sbo;

    const int t    = threadIdx.x;
    const int base = blockIdx.x * NT;
    const int rows = min(NT, n - base);

    // ---- cooperative staging: perfectly coalesced float4 copies ----
    {
        const float4* h4 = reinterpret_cast<const float4*>(h0) + (size_t)base * 5;
        const float4* c4 = reinterpret_cast<const float4*>(c0) + (size_t)base * 5;
        const int nv = rows * 5;
        for (int w = t; w < nv; w += NT) {
            sH4[w] = h4[w];
            sC4[w] = c4[w];
        }
    }

    // ---- stage packed weights ----
    if (t < HID) {
        const int k  = t;
        const int rf = 20 + k, rg = 40 + k, ro = 60 + k;
        sPack[k][0]  = 0.5f * W_ih[2 * k];
        sPack[k][1]  = 0.5f * W_ih[2 * k + 1];
        sPack[k][2]  = 0.5f * (b_ih[k] + b_hh[k]);
        sPack[k][3]  = W_ih[2 * rg];
        sPack[k][4]  = W_ih[2 * rg + 1];
        sPack[k][5]  = b_ih[rg] + b_hh[rg];
        sPack[k][6]  = 0.5f * W_ih[2 * ro];
        sPack[k][7]  = 0.5f * W_ih[2 * ro + 1];
        sPack[k][8]  = 0.5f * (b_ih[ro] + b_hh[ro]);
        sPack[k][9]  = 0.5f * W_ih[2 * rf];
        sPack[k][10] = 0.5f * W_ih[2 * rf + 1];
        sPack[k][11] = 0.5f * (b_ih[rf] + b_hh[rf]);
        sPack[k][12] = W_out[k];
        sPack[k][13] = 0.0f; sPack[k][14] = 0.0f; sPack[k][15] = 0.0f;
    }
    for (int idx = t; idx < 1600; idx += NT) {
        int row = idx / 20;
        float s = (row >= 40 && row < 60) ? 1.0f : 0.5f;
        sWhh[idx] = W_hh[idx] * s;
    }
    if (t == 0) sbo = b_out[0];

    // prefetch this thread's scalar inputs while staging settles
    float g = 0.0f, p = 0.0f;
    const int i = base + t;
    const bool active = (t < rows);
    if (active) { g = grads[i]; p = params[i]; }

    __syncthreads();
    if (!active) return;

    // ---- read h/c rows from smem: 5x LDS.128 each, conflict-free ----
    float cv[HID];
    float habs = 0.0f;
    #pragma unroll
    for (int q = 0; q < 5; q++) {
        float4 hh = sH4[t * 5 + q];
        habs += fabsf(hh.x) + fabsf(hh.y) + fabsf(hh.z) + fabsf(hh.w);
        float4 cc = sC4[t * 5 + q];
        cv[4 * q + 0] = cc.x; cv[4 * q + 1] = cc.y;
        cv[4 * q + 2] = cc.z; cv[4 * q + 3] = cc.w;
    }
    const bool hzero = (habs == 0.0f);

    float acc = sbo;

    if (__builtin_expect(hzero, 1)) {
        // ---- fast path: h0 row exactly zero -> skip W_hh matvec ----
        #pragma unroll
        for (int k = 0; k < HID; k++) {
            const float4* pk = reinterpret_cast<const float4*>(sPack[k]);
            float4 w0 = pk[0];   // wi_g, wi_p, bi, wg_g
            float4 w1 = pk[1];   // wg_p, bg, wo_g, wo_p
            float4 w2 = pk[2];   // bo, wf_g, wf_p, bf
            float4 w3 = pk[3];   // W_out[k], pad...

            float zi = fmaf(w0.x, g, fmaf(w0.y, p, w0.z));   // halved
            float zg = fmaf(w0.w, g, fmaf(w1.x, p, w1.y));
            float zo = fmaf(w1.z, g, fmaf(w1.w, p, w2.x));   // halved

            float ik = sig_from_half(zi);
            float gk = tanh_ap(zg);
            float ok = sig_from_half(zo);

            float c1 = ik * gk;
            float ck = cv[k];
            if (ck != 0.0f) {
                float zf = fmaf(w2.y, g, fmaf(w2.z, p, w2.w)); // halved
                c1 = fmaf(sig_from_half(zf), ck, c1);
            }
            acc = fmaf(ok * tanh_ap(c1), w3.x, acc);
        }
    } else {
        // ---- general path: full W_hh matvec (rare; h read from smem) ----
        const float* sHrow = reinterpret_cast<const float*>(sH4) + t * HID;
        #pragma unroll 1
        for (int k = 0; k < HID; k++) {
            const float* pk = sPack[k];
            float zi = fmaf(pk[0], g, fmaf(pk[1],  p, pk[2]));
            float zg = fmaf(pk[3], g, fmaf(pk[4],  p, pk[5]));
            float zo = fmaf(pk[6], g, fmaf(pk[7],  p, pk[8]));
            float zf = fmaf(pk[9], g, fmaf(pk[10], p, pk[11]));
            const int ri = k, rf = 20 + k, rg = 40 + k, ro = 60 + k;
            #pragma unroll 1
            for (int m = 0; m < HID; m++) {
                float hm = sHrow[m];
                zi = fmaf(sWhh[ri * HID + m], hm, zi);
                zf = fmaf(sWhh[rf * HID + m], hm, zf);
                zg = fmaf(sWhh[rg * HID + m], hm, zg);
                zo = fmaf(sWhh[ro * HID + m], hm, zo);
            }
            float ik = sig_from_half(zi);
            float fk = sig_from_half(zf);
            float gk = tanh_ap(zg);
            float ok = sig_from_half(zo);
            float c1 = fmaf(fk, cv[k], ik * gk);
            acc = fmaf(ok * tanh_ap(c1), pk[12], acc);
        }
    }

    out[i] = acc;
}

extern "C" void kernel_launch(void* const* d_in, const int* in_sizes, int n_in,
                              void* d_out, int out_size)
{
    const float* params = (const float*)d_in[0];
    const float* grads  = (const float*)d_in[1];
    const float* h0     = (const float*)d_in[2];
    const float* c0     = (const float*)d_in[3];
    const float* W_ih   = (const float*)d_in[4];
    const float* W_hh   = (const float*)d_in[5];
    const float* b_ih   = (const float*)d_in[6];
    const float* b_hh   = (const float*)d_in[7];
    const float* W_out  = (const float*)d_in[8];
    const float* b_out  = (const float*)d_in[9];
    float* out = (float*)d_out;

    int n = in_sizes[0];
    int blocks = (n + NT - 1) / NT;
    lstm_opt_kernel<<<blocks, NT>>>(params, grads, h0, c0,
                                    W_ih, W_hh, b_ih, b_hh,
                                    W_out, b_out, out, n);
}

// round 3
// speedup vs baseline: 1.0499x; 1.0216x over previous
#include <cuda_runtime.h>
#include <cuda_bf16.h>

#define HID 20
#define NT 256

__device__ __forceinline__ float tanh_ap(float x) {
    float y;
    asm("tanh.approx.f32 %0, %1;" : "=f"(y) : "f"(x));
    return y;
}

// sigmoid(z) where zh = 0.5*z was computed directly (0.5 folded into weights)
__device__ __forceinline__ float sig_from_half(float zh) {
    return fmaf(0.5f, tanh_ap(zh), 0.5f);
}

__global__ void __launch_bounds__(NT, 4)
lstm_opt_kernel(const float* __restrict__ params,
                const float* __restrict__ grads,
                const float* __restrict__ h0,
                const float* __restrict__ c0,
                const float* __restrict__ W_ih,   // [80,2]
                const float* __restrict__ W_hh,   // [80,20]
                const float* __restrict__ b_ih,   // [80]
                const float* __restrict__ b_hh,   // [80]
                const float* __restrict__ W_out,  // [20]
                const float* __restrict__ b_out,  // [1]
                float* __restrict__ out,
                int n)
{
    // Single reusable staging buffer: 256 rows x 20 floats (as float4, stride-5
    // granules -> conflict-free for both the coalesced fill and per-row reads).
    __shared__ float4 sStage[NT * 5];
    // Per-k packed weights: 4x LDS.128 broadcast per k.
    // [0]=wi_g [1]=wi_p [2]=bi(h) | [3]=wg_g [4]=wg_p [5]=bg |
    // [6]=wo_g [7]=wo_p [8]=bo(h) | [9]=wf_g [10]=wf_p [11]=bf(h) |
    // [12]=W_out[k] [13..15]=pad     ((h) = pre-halved for sigmoid trick)
    __shared__ float sPack[HID][16];
    __shared__ float sbo;

    const int t    = threadIdx.x;
    const int base = blockIdx.x * NT;
    const int rows = min(NT, n - base);
    const int nv   = rows * 5;
    const bool active = (t < rows);
    const int i = base + t;

    // ---- stage packed weights ----
    if (t < HID) {
        const int k  = t;
        const int rf = 20 + k, rg = 40 + k, ro = 60 + k;
        sPack[k][0]  = 0.5f * W_ih[2 * k];
        sPack[k][1]  = 0.5f * W_ih[2 * k + 1];
        sPack[k][2]  = 0.5f * (b_ih[k] + b_hh[k]);
        sPack[k][3]  = W_ih[2 * rg];
        sPack[k][4]  = W_ih[2 * rg + 1];
        sPack[k][5]  = b_ih[rg] + b_hh[rg];
        sPack[k][6]  = 0.5f * W_ih[2 * ro];
        sPack[k][7]  = 0.5f * W_ih[2 * ro + 1];
        sPack[k][8]  = 0.5f * (b_ih[ro] + b_hh[ro]);
        sPack[k][9]  = 0.5f * W_ih[2 * rf];
        sPack[k][10] = 0.5f * W_ih[2 * rf + 1];
        sPack[k][11] = 0.5f * (b_ih[rf] + b_hh[rf]);
        sPack[k][12] = W_out[k];
        sPack[k][13] = 0.0f; sPack[k][14] = 0.0f; sPack[k][15] = 0.0f;
    }
    if (t == 0) sbo = b_out[0];

    // prefetch this thread's scalar inputs (independent of staging)
    float g = 0.0f, p = 0.0f;
    if (active) { g = grads[i]; p = params[i]; }

    // ---- stage c0 (coalesced), read row into regs ----
    {
        const float4* c4 = reinterpret_cast<const float4*>(c0) + (size_t)base * 5;
        for (int w = t; w < nv; w += NT) sStage[w] = c4[w];
    }
    __syncthreads();

    float cv[HID];
    #pragma unroll
    for (int q = 0; q < 5; q++) {
        float4 cc = sStage[t * 5 + q];
        cv[4 * q + 0] = cc.x; cv[4 * q + 1] = cc.y;
        cv[4 * q + 2] = cc.z; cv[4 * q + 3] = cc.w;
    }
    __syncthreads();  // everyone done reading c before overwrite

    // ---- stage h0 (coalesced) into the same buffer ----
    {
        const float4* h4 = reinterpret_cast<const float4*>(h0) + (size_t)base * 5;
        for (int w = t; w < nv; w += NT) sStage[w] = h4[w];
    }
    __syncthreads();

    if (!active) return;

    // h-row zero test (fast path needs only this; values stay in smem)
    float habs = 0.0f;
    #pragma unroll
    for (int q = 0; q < 5; q++) {
        float4 hh = sStage[t * 5 + q];
        habs += fabsf(hh.x) + fabsf(hh.y) + fabsf(hh.z) + fabsf(hh.w);
    }
    const bool hzero = (habs == 0.0f);

    float acc = sbo;

    if (__builtin_expect(hzero, 1)) {
        // ---- fast path: h0 row exactly zero -> skip W_hh matvec ----
        #pragma unroll
        for (int k = 0; k < HID; k++) {
            const float4* pk = reinterpret_cast<const float4*>(sPack[k]);
            float4 w0 = pk[0];   // wi_g, wi_p, bi, wg_g
            float4 w1 = pk[1];   // wg_p, bg, wo_g, wo_p
            float4 w2 = pk[2];   // bo, wf_g, wf_p, bf
            float4 w3 = pk[3];   // W_out[k], pad...

            float zi = fmaf(w0.x, g, fmaf(w0.y, p, w0.z));   // halved
            float zg = fmaf(w0.w, g, fmaf(w1.x, p, w1.y));
            float zo = fmaf(w1.z, g, fmaf(w1.w, p, w2.x));   // halved

            float ik = sig_from_half(zi);
            float gk = tanh_ap(zg);
            float ok = sig_from_half(zo);

            float c1 = ik * gk;
            float ck = cv[k];
            if (ck != 0.0f) {
                float zf = fmaf(w2.y, g, fmaf(w2.z, p, w2.w)); // halved
                c1 = fmaf(sig_from_half(zf), ck, c1);
            }
            acc = fmaf(ok * tanh_ap(c1), w3.x, acc);
        }
    } else {
        // ---- general path: full W_hh matvec (cold; W_hh via L2) ----
        const float* sHrow = reinterpret_cast<const float*>(sStage) + t * HID;
        #pragma unroll 1
        for (int k = 0; k < HID; k++) {
            const float* pk = sPack[k];
            float zi = fmaf(pk[0], g, fmaf(pk[1],  p, pk[2]));   // halved
            float zg = fmaf(pk[3], g, fmaf(pk[4],  p, pk[5]));
            float zo = fmaf(pk[6], g, fmaf(pk[7],  p, pk[8]));   // halved
            float zf = fmaf(pk[9], g, fmaf(pk[10], p, pk[11]));  // halved
            const int ri = k, rf = 20 + k, rg = 40 + k, ro = 60 + k;
            #pragma unroll 1
            for (int m = 0; m < HID; m++) {
                float hm = sHrow[m];
                zi = fmaf(0.5f * __ldg(&W_hh[ri * HID + m]), hm, zi);
                zf = fmaf(0.5f * __ldg(&W_hh[rf * HID + m]), hm, zf);
                zg = fmaf(       __ldg(&W_hh[rg * HID + m]), hm, zg);
                zo = fmaf(0.5f * __ldg(&W_hh[ro * HID + m]), hm, zo);
            }
            float ik = sig_from_half(zi);
            float fk = sig_from_half(zf);
            float gk = tanh_ap(zg);
            float ok = sig_from_half(zo);
            float c1 = fmaf(fk, cv[k], ik * gk);
            acc = fmaf(ok * tanh_ap(c1), pk[12], acc);
        }
    }

    out[i] = acc;
}

extern "C" void kernel_launch(void* const* d_in, const int* in_sizes, int n_in,
                              void* d_out, int out_size)
{
    const float* params = (const float*)d_in[0];
    const float* grads  = (const float*)d_in[1];
    const float* h0     = (const float*)d_in[2];
    const float* c0     = (const float*)d_in[3];
    const float* W_ih   = (const float*)d_in[4];
    const float* W_hh   = (const float*)d_in[5];
    const float* b_ih   = (const float*)d_in[6];
    const float* b_hh   = (const float*)d_in[7];
    const float* W_out  = (const float*)d_in[8];
    const float* b_out  = (const float*)d_in[9];
    float* out = (float*)d_out;

    int n = in_sizes[0];
    int blocks = (n + NT - 1) / NT;
    lstm_opt_kernel<<<blocks, NT>>>(params, grads, h0, c0,
                                    W_ih, W_hh, b_ih, b_hh,
                                    W_out, b_out, out, n);
}